// round 2
// baseline (speedup 1.0000x reference)
#include <cuda_runtime.h>
#include <math.h>

// Problem constants
#define BATCH   2
#define SEQ     2048
#define HEADS   16
#define DIMS    64
#define IN_D    1024
#define MROWS   (BATCH*SEQ)       // 4096
#define FOLD    512               // folded width (KV_HEADS*DIMS = HEADS*32)

// Scratch (device globals; no allocation allowed)
__device__ float g_XQf[MROWS*FOLD];   // folded+rope'd Q  [4096,512]
__device__ float g_XK [MROWS*FOLD];   // rope'd K         [4096,512]
__device__ float g_XV [MROWS*FOLD];   // V                [4096,512]
__device__ float g_CTX[MROWS*FOLD];   // attention ctx    [4096,512]
__device__ float g_WoF[FOLD*IN_D];    // folded Wo        [512,1024]

#define TWO_PI 6.283185307179586476925287

// ---------------------------------------------------------------------------
// Kernel 1: fused QKV projection. C[4096, 2048] where cols [0,1024)=q@Wq,
// [1024,1536)=q@Wk, [1536,2048)=q@Wv. Epilogue applies RoPE (+Q fold).
// Tiles: BM=BN=64, BK=16, 256 threads, 4x4 per thread.
// ---------------------------------------------------------------------------
__global__ __launch_bounds__(256) void gemm_qkv(
    const float* __restrict__ A,
    const float* __restrict__ Wq,
    const float* __restrict__ Wk,
    const float* __restrict__ Wv)
{
    __shared__ float As[16][65];
    __shared__ float Bs[16][64];

    const int tid = threadIdx.x;
    const int tx = tid & 15, ty = tid >> 4;
    const int m_base = blockIdx.y * 64;
    const int n_base = blockIdx.x * 64;

    const float* Bmat; int bcol0, bld;
    if (n_base < 1024)      { Bmat = Wq; bcol0 = n_base;        bld = 1024; }
    else if (n_base < 1536) { Bmat = Wk; bcol0 = n_base - 1024; bld = 512;  }
    else                    { Bmat = Wv; bcol0 = n_base - 1536; bld = 512;  }

    float acc[4][4] = {};

    const int arow = tid >> 2, af4 = tid & 3;      // A tile loader mapping
    const int brow = tid >> 4, bf4 = tid & 15;     // B tile loader mapping

    for (int k0 = 0; k0 < IN_D; k0 += 16) {
        float4 a = *(const float4*)(A + (m_base + arow) * IN_D + k0 + af4 * 4);
        As[af4*4+0][arow] = a.x; As[af4*4+1][arow] = a.y;
        As[af4*4+2][arow] = a.z; As[af4*4+3][arow] = a.w;
        *(float4*)&Bs[brow][bf4*4] =
            *(const float4*)(Bmat + (k0 + brow) * bld + bcol0 + bf4 * 4);
        __syncthreads();
        #pragma unroll
        for (int k = 0; k < 16; k++) {
            float ra[4], rb[4];
            #pragma unroll
            for (int i = 0; i < 4; i++) ra[i] = As[k][ty*4+i];
            #pragma unroll
            for (int j = 0; j < 4; j++) rb[j] = Bs[k][tx*4+j];
            #pragma unroll
            for (int i = 0; i < 4; i++)
                #pragma unroll
                for (int j = 0; j < 4; j++)
                    acc[i][j] += ra[i] * rb[j];
        }
        __syncthreads();
    }

    // Epilogue: RoPE + fold. Thread owns 4 consecutive cols => 2 rope pairs.
    #pragma unroll
    for (int p = 0; p < 2; p++) {
        const int n = n_base + tx * 4 + 2 * p;   // even
        if (n < 1024) {
            // Q: rope over dim=1024, pair index ii = n/2; store folded value
            const int ii = n >> 1;
            const double theta = pow(10000.0, -(double)n / 1024.0);
            #pragma unroll
            for (int i = 0; i < 4; i++) {
                const int m = m_base + ty * 4 + i;
                const int sidx = m & (SEQ - 1);
                const double ang = fmod((double)(sidx + 1) * theta, TWO_PI);
                float sn, c; sincosf((float)ang, &sn, &c);
                const float xe = acc[i][2*p], xo = acc[i][2*p+1];
                g_XQf[m * FOLD + ii] = xe * (c + sn) + xo * (c - sn);
            }
        } else if (n < 1536) {
            // K: rope over dim=512
            const int kk = n - 1024;
            const double theta = pow(10000.0, -(double)kk / 512.0);
            #pragma unroll
            for (int i = 0; i < 4; i++) {
                const int m = m_base + ty * 4 + i;
                const int sidx = m & (SEQ - 1);
                const double ang = fmod((double)(sidx + 1) * theta, TWO_PI);
                float sn, c; sincosf((float)ang, &sn, &c);
                const float xe = acc[i][2*p], xo = acc[i][2*p+1];
                g_XK[m * FOLD + kk]     = xe * c - xo * sn;
                g_XK[m * FOLD + kk + 1] = xe * sn + xo * c;
            }
        } else {
            const int vv = n - 1536;
            #pragma unroll
            for (int i = 0; i < 4; i++) {
                const int m = m_base + ty * 4 + i;
                g_XV[m * FOLD + vv]     = acc[i][2*p];
                g_XV[m * FOLD + vv + 1] = acc[i][2*p+1];
            }
        }
    }
}

// ---------------------------------------------------------------------------
// Kernel 2: fold Wo rows pairwise: WoF[k,n] = Wo[2k,n] + Wo[2k+1,n]
// ---------------------------------------------------------------------------
__global__ void fold_wo(const float* __restrict__ Wo)
{
    const int idx = blockIdx.x * 256 + threadIdx.x;   // < 512*1024
    const int k = idx >> 10, n = idx & 1023;
    g_WoF[idx] = Wo[(2*k) * IN_D + n] + Wo[(2*k + 1) * IN_D + n];
}

// ---------------------------------------------------------------------------
// Kernel 3: flash attention at folded head dim 32, online softmax.
// Block = 128 threads = 128 query rows; KV tiles of 32 in smem.
// grid: (SEQ/128, BATCH*HEADS)
// ---------------------------------------------------------------------------
__global__ __launch_bounds__(128) void attn()
{
    __shared__ float Ks[32][32];
    __shared__ float Vs[32][32];

    const int tid = threadIdx.x;
    const int h = blockIdx.y & (HEADS - 1);
    const int b = blockIdx.y >> 4;
    const int m = b * SEQ + blockIdx.x * 128 + tid;
    const int hoff = h * 32;
    const int kvbase = b * SEQ;

    float qf[32];
    #pragma unroll
    for (int j4 = 0; j4 < 8; j4++) {
        float4 v = *(const float4*)(g_XQf + m * FOLD + hoff + j4 * 4);
        qf[j4*4+0] = v.x; qf[j4*4+1] = v.y; qf[j4*4+2] = v.z; qf[j4*4+3] = v.w;
    }

    float mr = -INFINITY, l = 0.f;
    float ctx[32];
    #pragma unroll
    for (int j = 0; j < 32; j++) ctx[j] = 0.f;

    for (int t0 = 0; t0 < SEQ; t0 += 32) {
        __syncthreads();
        #pragma unroll
        for (int rep = 0; rep < 2; rep++) {
            const int idx = tid + rep * 128;       // 256 float4 per matrix
            const int r = idx >> 3, c4 = idx & 7;
            const long off = (long)(kvbase + t0 + r) * FOLD + hoff + c4 * 4;
            *(float4*)&Ks[r][c4*4] = *(const float4*)(g_XK + off);
            *(float4*)&Vs[r][c4*4] = *(const float4*)(g_XV + off);
        }
        __syncthreads();

        float s[32];
        #pragma unroll
        for (int kk = 0; kk < 32; kk++) {
            float a = 0.f;
            #pragma unroll
            for (int j = 0; j < 32; j++) a += qf[j] * Ks[kk][j];
            s[kk] = a * 0.5f;                       // scale = (DIMS/HEADS)^-0.5
        }
        float tm = s[0];
        #pragma unroll
        for (int kk = 1; kk < 32; kk++) tm = fmaxf(tm, s[kk]);
        const float mn = fmaxf(mr, tm);
        const float corr = __expf(mr - mn);
        l *= corr;
        #pragma unroll
        for (int j = 0; j < 32; j++) ctx[j] *= corr;
        #pragma unroll
        for (int kk = 0; kk < 32; kk++) {
            const float p = __expf(s[kk] - mn);
            l += p;
            #pragma unroll
            for (int j = 0; j < 32; j++) ctx[j] += p * Vs[kk][j];
        }
        mr = mn;
    }

    const float inv = 1.f / l;
    #pragma unroll
    for (int j4 = 0; j4 < 8; j4++) {
        float4 v;
        v.x = ctx[j4*4+0] * inv; v.y = ctx[j4*4+1] * inv;
        v.z = ctx[j4*4+2] * inv; v.w = ctx[j4*4+3] * inv;
        *(float4*)(g_CTX + m * FOLD + hoff + j4 * 4) = v;
    }
}

// ---------------------------------------------------------------------------
// Kernel 4: output projection: CTX[4096,512] @ WoF[512,1024] -> out
// ---------------------------------------------------------------------------
__global__ __launch_bounds__(256) void gemm_out(float* __restrict__ C)
{
    __shared__ float As[16][65];
    __shared__ float Bs[16][64];

    const int tid = threadIdx.x;
    const int tx = tid & 15, ty = tid >> 4;
    const int m_base = blockIdx.y * 64;
    const int n_base = blockIdx.x * 64;

    float acc[4][4] = {};
    const int arow = tid >> 2, af4 = tid & 3;
    const int brow = tid >> 4, bf4 = tid & 15;

    for (int k0 = 0; k0 < FOLD; k0 += 16) {
        float4 a = *(const float4*)(g_CTX + (m_base + arow) * FOLD + k0 + af4 * 4);
        As[af4*4+0][arow] = a.x; As[af4*4+1][arow] = a.y;
        As[af4*4+2][arow] = a.z; As[af4*4+3][arow] = a.w;
        *(float4*)&Bs[brow][bf4*4] =
            *(const float4*)(g_WoF + (k0 + brow) * IN_D + n_base + bf4 * 4);
        __syncthreads();
        #pragma unroll
        for (int k = 0; k < 16; k++) {
            float ra[4], rb[4];
            #pragma unroll
            for (int i = 0; i < 4; i++) ra[i] = As[k][ty*4+i];
            #pragma unroll
            for (int j = 0; j < 4; j++) rb[j] = Bs[k][tx*4+j];
            #pragma unroll
            for (int i = 0; i < 4; i++)
                #pragma unroll
                for (int j = 0; j < 4; j++)
                    acc[i][j] += ra[i] * rb[j];
        }
        __syncthreads();
    }

    #pragma unroll
    for (int i = 0; i < 4; i++) {
        const int m = m_base + ty * 4 + i;
        float4 v;
        v.x = acc[i][0]; v.y = acc[i][1]; v.z = acc[i][2]; v.w = acc[i][3];
        *(float4*)(C + m * IN_D + n_base + tx * 4) = v;
    }
}

// ---------------------------------------------------------------------------
extern "C" void kernel_launch(void* const* d_in, const int* in_sizes, int n_in,
                              void* d_out, int out_size)
{
    const float* q  = (const float*)d_in[0];
    const float* Wq = (const float*)d_in[1];
    const float* Wk = (const float*)d_in[2];
    const float* Wv = (const float*)d_in[3];
    const float* Wo = (const float*)d_in[4];

    gemm_qkv<<<dim3(32, 64), 256>>>(q, Wq, Wk, Wv);          // [4096,2048] proj + rope
    fold_wo <<<2048, 256>>>(Wo);                             // WoF
    attn    <<<dim3(SEQ / 128, BATCH * HEADS), 128>>>();     // flash attention D=32
    gemm_out<<<dim3(IN_D / 64, MROWS / 64), 256>>>((float*)d_out);
}

// round 7
// speedup vs baseline: 1.0531x; 1.0531x over previous
#include <cuda_runtime.h>
#include <math.h>
#include <cstdint>

// Problem constants
#define BATCH   2
#define SEQ     2048
#define HEADS   16
#define IN_D    1024
#define MROWS   (BATCH*SEQ)       // 4096
#define FOLD    512               // folded width

// Scratch (device globals; no allocation allowed)
__device__ __align__(256) float g_XQf[MROWS*FOLD];   // folded+rope'd Q  [4096,512]
__device__ __align__(256) float g_XK [MROWS*FOLD];   // rope'd K         [4096,512]
__device__ __align__(256) float g_XV [MROWS*FOLD];   // V                [4096,512]
__device__ __align__(256) float g_CTX[MROWS*FOLD];   // attention ctx    [4096,512]
__device__ __align__(256) float g_WoF[FOLD*IN_D];    // folded Wo        [512,1024]
__device__ float g_theta[768];                       // [0,512): Q pair thetas, [512,768): K

// ---------------------------------------------------------------------------
// tf32 helpers (mma.sync path — sm_80+ PTX, valid on plain sm_103 target)
// ---------------------------------------------------------------------------
__device__ __forceinline__ uint32_t f2tf32(float x) {
    uint32_t o;
    asm("cvt.rna.tf32.f32 %0, %1;" : "=r"(o) : "f"(x));
    return o;
}

__device__ __forceinline__ void mma_tf32(float* d, const uint32_t* a, const uint32_t* b) {
    asm volatile(
        "mma.sync.aligned.m16n8k8.row.col.f32.tf32.tf32.f32 "
        "{%0,%1,%2,%3}, {%4,%5,%6,%7}, {%8,%9}, {%0,%1,%2,%3};"
        : "+f"(d[0]), "+f"(d[1]), "+f"(d[2]), "+f"(d[3])
        : "r"(a[0]), "r"(a[1]), "r"(a[2]), "r"(a[3]), "r"(b[0]), "r"(b[1]));
}

// Smem strides (floats) chosen for conflict-free fragment LDS:
//   A[m][k]: stride 36 -> bank(m,k) = (4m+k)%32, distinct over the 8x4 lane grid
//   B[k][n]: stride 136 -> bank(k,n) = (8k+n)%32, distinct over the 4x8 lane grid
#define A_STR 36
#define B_STR 136
#define A_ELEMS (128 * A_STR)
#define B_ELEMS (32 * B_STR)
#define GSMEM_BYTES ((2 * A_ELEMS + 2 * B_ELEMS) * 4)   // hi+lo tiles: 71680 B

// ---------------------------------------------------------------------------
// 3xTF32 tile GEMM mainloop. CTA tile 128x128, BK=32, 256 threads (8 warps,
// warp grid 2x4, warp tile 64x32). Each operand split into hi/lo tf32 parts;
// c += Ahi*Bhi + Ahi*Blo + Alo*Bhi  (~fp32 accuracy).
// ---------------------------------------------------------------------------
__device__ __forceinline__ void gemm_mainloop(
    float* sm,
    const float* __restrict__ A, int lda,
    const float* __restrict__ B, int ldb,
    int nk, int tid, float c[4][4][4])
{
    float* As_hi = sm;
    float* As_lo = sm + A_ELEMS;
    float* Bs_hi = sm + 2 * A_ELEMS;
    float* Bs_lo = sm + 2 * A_ELEMS + B_ELEMS;

    const int wid = tid >> 5, lane = tid & 31;
    const int wm = wid & 1, wn = wid >> 1;
    const int tq = lane >> 2, tr = lane & 3;

    for (int k0 = 0; k0 < nk; k0 += 32) {
        // A tile: 128x32, float4 loads, split hi/lo, store [m][k] stride 36
        #pragma unroll
        for (int i = 0; i < 4; i++) {
            int e = i * 256 + tid;
            int r = e >> 3, c4 = e & 7;
            float4 v = *(const float4*)(A + (long)r * lda + k0 + c4 * 4);
            uint32_t* dh = (uint32_t*)&As_hi[r * A_STR + c4 * 4];
            uint32_t* dl = (uint32_t*)&As_lo[r * A_STR + c4 * 4];
            const float vv[4] = {v.x, v.y, v.z, v.w};
            #pragma unroll
            for (int q = 0; q < 4; q++) {
                uint32_t h = f2tf32(vv[q]);
                dh[q] = h;
                dl[q] = f2tf32(vv[q] - __uint_as_float(h));
            }
        }
        // B tile: 32x128, coalesced rows, split hi/lo, store [k][n] stride 136
        #pragma unroll
        for (int i = 0; i < 4; i++) {
            int e = i * 256 + tid;
            int kr = e >> 5, c4 = e & 31;
            float4 v = *(const float4*)(B + (long)(k0 + kr) * ldb + c4 * 4);
            uint32_t* dh = (uint32_t*)&Bs_hi[kr * B_STR + c4 * 4];
            uint32_t* dl = (uint32_t*)&Bs_lo[kr * B_STR + c4 * 4];
            const float vv[4] = {v.x, v.y, v.z, v.w};
            #pragma unroll
            for (int q = 0; q < 4; q++) {
                uint32_t h = f2tf32(vv[q]);
                dh[q] = h;
                dl[q] = f2tf32(vv[q] - __uint_as_float(h));
            }
        }
        __syncthreads();

        #pragma unroll
        for (int ks = 0; ks < 4; ks++) {
            uint32_t ah[4][4], al[4][4], bh[4][2], bl[4][2];
            const uint32_t* Ahu = (const uint32_t*)As_hi;
            const uint32_t* Alu = (const uint32_t*)As_lo;
            const uint32_t* Bhu = (const uint32_t*)Bs_hi;
            const uint32_t* Blu = (const uint32_t*)Bs_lo;
            #pragma unroll
            for (int mi = 0; mi < 4; mi++) {
                int base = (wm * 64 + mi * 16 + tq) * A_STR + ks * 8 + tr;
                ah[mi][0] = Ahu[base];              al[mi][0] = Alu[base];
                ah[mi][1] = Ahu[base + 8 * A_STR];  al[mi][1] = Alu[base + 8 * A_STR];
                ah[mi][2] = Ahu[base + 4];          al[mi][2] = Alu[base + 4];
                ah[mi][3] = Ahu[base + 8 * A_STR + 4]; al[mi][3] = Alu[base + 8 * A_STR + 4];
            }
            #pragma unroll
            for (int ni = 0; ni < 4; ni++) {
                int base = (ks * 8 + tr) * B_STR + wn * 32 + ni * 8 + tq;
                bh[ni][0] = Bhu[base];              bl[ni][0] = Blu[base];
                bh[ni][1] = Bhu[base + 4 * B_STR];  bl[ni][1] = Blu[base + 4 * B_STR];
            }
            #pragma unroll
            for (int mi = 0; mi < 4; mi++)
                #pragma unroll
                for (int ni = 0; ni < 4; ni++) {
                    mma_tf32(c[mi][ni], al[mi], bh[ni]);   // lo*hi correction
                    mma_tf32(c[mi][ni], ah[mi], bl[ni]);   // hi*lo correction
                    mma_tf32(c[mi][ni], ah[mi], bh[ni]);   // main term
                }
        }
        __syncthreads();
    }
}

// ---------------------------------------------------------------------------
// Kernel 1: QKV projection (3xTF32 tensor cores) + RoPE/fold on fragments.
// grid (16, 32): n_base = bx*128 (cols [0,1024)=Q, [1024,1536)=K, rest=V).
// ---------------------------------------------------------------------------
__global__ __launch_bounds__(256) void gemm_qkv(
    const float* __restrict__ A,
    const float* __restrict__ Wq,
    const float* __restrict__ Wk,
    const float* __restrict__ Wv)
{
    extern __shared__ float sm[];

    const int tid = threadIdx.x;
    const int wid = tid >> 5, lane = tid & 31;
    const int wm = wid & 1, wn = wid >> 1;
    const int tq = lane >> 2, tr = lane & 3;
    const int m_base = blockIdx.y * 128;
    const int n_base = blockIdx.x * 128;

    const float* Bm; int ldb, region;
    if (n_base < 1024)      { Bm = Wq + n_base;          ldb = 1024; region = 0; }
    else if (n_base < 1536) { Bm = Wk + (n_base - 1024); ldb = 512;  region = 1; }
    else                    { Bm = Wv + (n_base - 1536); ldb = 512;  region = 2; }

    float c[4][4][4];
    #pragma unroll
    for (int i = 0; i < 4; i++)
        #pragma unroll
        for (int j = 0; j < 4; j++)
            #pragma unroll
            for (int r = 0; r < 4; r++) c[i][j][r] = 0.f;

    gemm_mainloop(sm, A + (long)m_base * IN_D, IN_D, Bm, ldb, IN_D, tid, c);

    // Epilogue: fragment (c0,c1)/(c2,c3) are (even,odd) column pairs.
    #pragma unroll
    for (int mi = 0; mi < 4; mi++) {
        #pragma unroll
        for (int h = 0; h < 2; h++) {
            const int m = m_base + wm * 64 + mi * 16 + tq + h * 8;
            const float pos = (float)((m & (SEQ - 1)) + 1);
            #pragma unroll
            for (int ni = 0; ni < 4; ni++) {
                const float xe = c[mi][ni][2 * h];
                const float xo = c[mi][ni][2 * h + 1];
                const int ncol = n_base + wn * 32 + ni * 8 + 2 * tr;  // even global col
                if (region == 0) {
                    const int ii = ncol >> 1;
                    float sn, cs; sincosf(pos * g_theta[ii], &sn, &cs);
                    g_XQf[(long)m * FOLD + ii] = xe * (cs + sn) + xo * (cs - sn);
                } else if (region == 1) {
                    const int kk = ncol - 1024;
                    float sn, cs; sincosf(pos * g_theta[512 + (kk >> 1)], &sn, &cs);
                    *(float2*)(g_XK + (long)m * FOLD + kk) =
                        make_float2(xe * cs - xo * sn, xe * sn + xo * cs);
                } else {
                    const int vv = ncol - 1536;
                    *(float2*)(g_XV + (long)m * FOLD + vv) = make_float2(xe, xo);
                }
            }
        }
    }
}

// ---------------------------------------------------------------------------
// Kernel 2: prep — fold Wo pairwise + RoPE theta table (f64-accurate)
// ---------------------------------------------------------------------------
__global__ void prep(const float* __restrict__ Wo)
{
    const int idx = blockIdx.x * 256 + threadIdx.x;   // < 512*1024
    const int k = idx >> 10, n = idx & 1023;
    g_WoF[idx] = Wo[(2 * k) * IN_D + n] + Wo[(2 * k + 1) * IN_D + n];
    if (idx < 512)
        g_theta[idx] = (float)pow(10000.0, -(double)(2 * idx) / 1024.0);
    else if (idx < 768)
        g_theta[idx] = (float)pow(10000.0, -(double)(2 * (idx - 512)) / 512.0);
}

// ---------------------------------------------------------------------------
// Kernel 3: flash attention, folded head dim 32 (known-good from R1)
// ---------------------------------------------------------------------------
__global__ __launch_bounds__(128) void attn()
{
    __shared__ float Ks[32][32];
    __shared__ float Vs[32][32];

    const int tid = threadIdx.x;
    const int h = blockIdx.y & (HEADS - 1);
    const int b = blockIdx.y >> 4;
    const int m = b * SEQ + blockIdx.x * 128 + tid;
    const int hoff = h * 32;
    const int kvbase = b * SEQ;

    float qf[32];
    #pragma unroll
    for (int j4 = 0; j4 < 8; j4++) {
        float4 v = *(const float4*)(g_XQf + (long)m * FOLD + hoff + j4 * 4);
        qf[j4*4+0] = v.x; qf[j4*4+1] = v.y; qf[j4*4+2] = v.z; qf[j4*4+3] = v.w;
    }

    float mr = -INFINITY, l = 0.f;
    float ctx[32];
    #pragma unroll
    for (int j = 0; j < 32; j++) ctx[j] = 0.f;

    for (int t0 = 0; t0 < SEQ; t0 += 32) {
        __syncthreads();
        #pragma unroll
        for (int rep = 0; rep < 2; rep++) {
            const int idx = tid + rep * 128;
            const int r = idx >> 3, c4 = idx & 7;
            const long off = (long)(kvbase + t0 + r) * FOLD + hoff + c4 * 4;
            *(float4*)&Ks[r][c4*4] = *(const float4*)(g_XK + off);
            *(float4*)&Vs[r][c4*4] = *(const float4*)(g_XV + off);
        }
        __syncthreads();

        float s[32];
        #pragma unroll
        for (int kk = 0; kk < 32; kk++) {
            float a = 0.f;
            #pragma unroll
            for (int j = 0; j < 32; j++) a += qf[j] * Ks[kk][j];
            s[kk] = a * 0.5f;
        }
        float tm = s[0];
        #pragma unroll
        for (int kk = 1; kk < 32; kk++) tm = fmaxf(tm, s[kk]);
        const float mn = fmaxf(mr, tm);
        const float corr = __expf(mr - mn);
        l *= corr;
        #pragma unroll
        for (int j = 0; j < 32; j++) ctx[j] *= corr;
        #pragma unroll
        for (int kk = 0; kk < 32; kk++) {
            const float p = __expf(s[kk] - mn);
            l += p;
            #pragma unroll
            for (int j = 0; j < 32; j++) ctx[j] += p * Vs[kk][j];
        }
        mr = mn;
    }

    const float inv = 1.f / l;
    #pragma unroll
    for (int j4 = 0; j4 < 8; j4++) {
        float4 v;
        v.x = ctx[j4*4+0] * inv; v.y = ctx[j4*4+1] * inv;
        v.z = ctx[j4*4+2] * inv; v.w = ctx[j4*4+3] * inv;
        *(float4*)(g_CTX + (long)m * FOLD + hoff + j4 * 4) = v;
    }
}

// ---------------------------------------------------------------------------
// Kernel 4: output projection CTX[4096,512] @ WoF[512,1024] (3xTF32)
// grid (8, 32), 256 threads.
// ---------------------------------------------------------------------------
__global__ __launch_bounds__(256) void gemm_out(float* __restrict__ C)
{
    extern __shared__ float sm[];

    const int tid = threadIdx.x;
    const int wid = tid >> 5, lane = tid & 31;
    const int wm = wid & 1, wn = wid >> 1;
    const int tq = lane >> 2, tr = lane & 3;
    const int m_base = blockIdx.y * 128;
    const int n_base = blockIdx.x * 128;

    float c[4][4][4];
    #pragma unroll
    for (int i = 0; i < 4; i++)
        #pragma unroll
        for (int j = 0; j < 4; j++)
            #pragma unroll
            for (int r = 0; r < 4; r++) c[i][j][r] = 0.f;

    gemm_mainloop(sm, g_CTX + (long)m_base * FOLD, FOLD,
                  g_WoF + n_base, IN_D, FOLD, tid, c);

    #pragma unroll
    for (int mi = 0; mi < 4; mi++)
        #pragma unroll
        for (int h = 0; h < 2; h++) {
            const int m = m_base + wm * 64 + mi * 16 + tq + h * 8;
            #pragma unroll
            for (int ni = 0; ni < 4; ni++) {
                const int col = n_base + wn * 32 + ni * 8 + 2 * tr;
                *(float2*)(C + (long)m * IN_D + col) =
                    make_float2(c[mi][ni][2 * h], c[mi][ni][2 * h + 1]);
            }
        }
}

// ---------------------------------------------------------------------------
extern "C" void kernel_launch(void* const* d_in, const int* in_sizes, int n_in,
                              void* d_out, int out_size)
{
    const float* q  = (const float*)d_in[0];
    const float* Wq = (const float*)d_in[1];
    const float* Wk = (const float*)d_in[2];
    const float* Wv = (const float*)d_in[3];
    const float* Wo = (const float*)d_in[4];

    static int configured = 0;
    if (!configured) {
        cudaFuncSetAttribute(gemm_qkv, cudaFuncAttributeMaxDynamicSharedMemorySize, GSMEM_BYTES);
        cudaFuncSetAttribute(gemm_out, cudaFuncAttributeMaxDynamicSharedMemorySize, GSMEM_BYTES);
        configured = 1;
    }

    prep    <<<2048, 256>>>(Wo);                                    // WoF + theta table
    gemm_qkv<<<dim3(16, 32), 256, GSMEM_BYTES>>>(q, Wq, Wk, Wv);    // 3xTF32 + rope
    attn    <<<dim3(SEQ / 128, BATCH * HEADS), 128>>>();            // flash attention D=32
    gemm_out<<<dim3(8, 32), 256, GSMEM_BYTES>>>((float*)d_out);     // 3xTF32
}

// round 8
// speedup vs baseline: 1.5558x; 1.4774x over previous
#include <cuda_runtime.h>
#include <math.h>
#include <cstdint>

// Problem constants
#define BATCH   2
#define SEQ     2048
#define HEADS   16
#define IN_D    1024
#define MROWS   (BATCH*SEQ)       // 4096
#define FOLD    512               // folded width

// Scratch (device globals; no allocation allowed)
__device__ __align__(256) float g_XQf[MROWS*FOLD];   // folded+rope'd Q  [4096,512]
__device__ __align__(256) float g_XK [MROWS*FOLD];   // rope'd K         [4096,512]
__device__ __align__(256) float g_XV [MROWS*FOLD];   // V                [4096,512]
__device__ __align__(256) float g_CTX[MROWS*FOLD];   // attention ctx    [4096,512]
__device__ __align__(256) float g_WoF[FOLD*IN_D];    // folded Wo        [512,1024]
__device__ float g_theta[768];                       // [0,512): Q pair thetas, [512,768): K

// ---------------------------------------------------------------------------
// tf32 helpers (mma.sync path — sm_80+ PTX, valid on plain sm_103 target)
// ---------------------------------------------------------------------------
__device__ __forceinline__ uint32_t f2tf32(float x) {
    uint32_t o;
    asm("cvt.rna.tf32.f32 %0, %1;" : "=r"(o) : "f"(x));
    return o;
}

__device__ __forceinline__ void mma_tf32(float* d, const uint32_t* a, const uint32_t* b) {
    asm volatile(
        "mma.sync.aligned.m16n8k8.row.col.f32.tf32.tf32.f32 "
        "{%0,%1,%2,%3}, {%4,%5,%6,%7}, {%8,%9}, {%0,%1,%2,%3};"
        : "+f"(d[0]), "+f"(d[1]), "+f"(d[2]), "+f"(d[3])
        : "r"(a[0]), "r"(a[1]), "r"(a[2]), "r"(a[3]), "r"(b[0]), "r"(b[1]));
}

// fast 2^t on the FMA/ALU pipes (no MUFU): magic-round + degree-5 Taylor.
// Valid for |t| < 2^21 and result in normal range; rel err ~2e-6.
__device__ __forceinline__ float exp2fast(float t) {
    float z = t + 12582912.0f;                 // 1.5*2^23: rounds t to int in low bits
    int   n = __float_as_int(z) - 0x4B400000;
    float f = t - (z - 12582912.0f);           // f in [-0.5, 0.5]
    float r = 1.0f + f*(0.69314718f + f*(0.24022651f + f*(0.05550411f
                  + f*(0.00961813f + f*0.00133336f))));
    return __int_as_float(__float_as_int(r) + (n << 23));
}

// Smem strides (floats) chosen for conflict-free fragment LDS:
//   A[m][k]: stride 36 -> bank(m,k) = (4m+k)%32, distinct over the 8x4 lane grid
//   B[k][n]: stride 136 -> bank(k,n) = (8k+n)%32, distinct over the 4x8 lane grid
#define A_STR 36
#define B_STR 136
#define A_ELEMS (128 * A_STR)
#define B_ELEMS (32 * B_STR)
#define GSMEM_BYTES ((2 * A_ELEMS + 2 * B_ELEMS) * 4)   // hi+lo tiles: 71680 B

// ---------------------------------------------------------------------------
// 3xTF32 tile GEMM mainloop (unchanged, known-good). CTA tile 128x128, BK=32,
// 256 threads (8 warps, 2x4), warp tile 64x32.
// ---------------------------------------------------------------------------
__device__ __forceinline__ void gemm_mainloop(
    float* sm,
    const float* __restrict__ A, int lda,
    const float* __restrict__ B, int ldb,
    int nk, int tid, float c[4][4][4])
{
    float* As_hi = sm;
    float* As_lo = sm + A_ELEMS;
    float* Bs_hi = sm + 2 * A_ELEMS;
    float* Bs_lo = sm + 2 * A_ELEMS + B_ELEMS;

    const int wid = tid >> 5, lane = tid & 31;
    const int wm = wid & 1, wn = wid >> 1;
    const int tq = lane >> 2, tr = lane & 3;

    for (int k0 = 0; k0 < nk; k0 += 32) {
        #pragma unroll
        for (int i = 0; i < 4; i++) {
            int e = i * 256 + tid;
            int r = e >> 3, c4 = e & 7;
            float4 v = *(const float4*)(A + (long)r * lda + k0 + c4 * 4);
            uint32_t* dh = (uint32_t*)&As_hi[r * A_STR + c4 * 4];
            uint32_t* dl = (uint32_t*)&As_lo[r * A_STR + c4 * 4];
            const float vv[4] = {v.x, v.y, v.z, v.w};
            #pragma unroll
            for (int q = 0; q < 4; q++) {
                uint32_t h = f2tf32(vv[q]);
                dh[q] = h;
                dl[q] = f2tf32(vv[q] - __uint_as_float(h));
            }
        }
        #pragma unroll
        for (int i = 0; i < 4; i++) {
            int e = i * 256 + tid;
            int kr = e >> 5, c4 = e & 31;
            float4 v = *(const float4*)(B + (long)(k0 + kr) * ldb + c4 * 4);
            uint32_t* dh = (uint32_t*)&Bs_hi[kr * B_STR + c4 * 4];
            uint32_t* dl = (uint32_t*)&Bs_lo[kr * B_STR + c4 * 4];
            const float vv[4] = {v.x, v.y, v.z, v.w};
            #pragma unroll
            for (int q = 0; q < 4; q++) {
                uint32_t h = f2tf32(vv[q]);
                dh[q] = h;
                dl[q] = f2tf32(vv[q] - __uint_as_float(h));
            }
        }
        __syncthreads();

        #pragma unroll
        for (int ks = 0; ks < 4; ks++) {
            uint32_t ah[4][4], al[4][4], bh[4][2], bl[4][2];
            const uint32_t* Ahu = (const uint32_t*)As_hi;
            const uint32_t* Alu = (const uint32_t*)As_lo;
            const uint32_t* Bhu = (const uint32_t*)Bs_hi;
            const uint32_t* Blu = (const uint32_t*)Bs_lo;
            #pragma unroll
            for (int mi = 0; mi < 4; mi++) {
                int base = (wm * 64 + mi * 16 + tq) * A_STR + ks * 8 + tr;
                ah[mi][0] = Ahu[base];              al[mi][0] = Alu[base];
                ah[mi][1] = Ahu[base + 8 * A_STR];  al[mi][1] = Alu[base + 8 * A_STR];
                ah[mi][2] = Ahu[base + 4];          al[mi][2] = Alu[base + 4];
                ah[mi][3] = Ahu[base + 8 * A_STR + 4]; al[mi][3] = Alu[base + 8 * A_STR + 4];
            }
            #pragma unroll
            for (int ni = 0; ni < 4; ni++) {
                int base = (ks * 8 + tr) * B_STR + wn * 32 + ni * 8 + tq;
                bh[ni][0] = Bhu[base];              bl[ni][0] = Blu[base];
                bh[ni][1] = Bhu[base + 4 * B_STR];  bl[ni][1] = Blu[base + 4 * B_STR];
            }
            #pragma unroll
            for (int mi = 0; mi < 4; mi++)
                #pragma unroll
                for (int ni = 0; ni < 4; ni++) {
                    mma_tf32(c[mi][ni], al[mi], bh[ni]);
                    mma_tf32(c[mi][ni], ah[mi], bl[ni]);
                    mma_tf32(c[mi][ni], ah[mi], bh[ni]);
                }
        }
        __syncthreads();
    }
}

// ---------------------------------------------------------------------------
// Kernel 1: QKV projection (3xTF32) + RoPE/fold on fragments (unchanged)
// ---------------------------------------------------------------------------
__global__ __launch_bounds__(256) void gemm_qkv(
    const float* __restrict__ A,
    const float* __restrict__ Wq,
    const float* __restrict__ Wk,
    const float* __restrict__ Wv)
{
    extern __shared__ float sm[];

    const int tid = threadIdx.x;
    const int wid = tid >> 5, lane = tid & 31;
    const int wm = wid & 1, wn = wid >> 1;
    const int tq = lane >> 2, tr = lane & 3;
    const int m_base = blockIdx.y * 128;
    const int n_base = blockIdx.x * 128;

    const float* Bm; int ldb, region;
    if (n_base < 1024)      { Bm = Wq + n_base;          ldb = 1024; region = 0; }
    else if (n_base < 1536) { Bm = Wk + (n_base - 1024); ldb = 512;  region = 1; }
    else                    { Bm = Wv + (n_base - 1536); ldb = 512;  region = 2; }

    float c[4][4][4];
    #pragma unroll
    for (int i = 0; i < 4; i++)
        #pragma unroll
        for (int j = 0; j < 4; j++)
            #pragma unroll
            for (int r = 0; r < 4; r++) c[i][j][r] = 0.f;

    gemm_mainloop(sm, A + (long)m_base * IN_D, IN_D, Bm, ldb, IN_D, tid, c);

    #pragma unroll
    for (int mi = 0; mi < 4; mi++) {
        #pragma unroll
        for (int h = 0; h < 2; h++) {
            const int m = m_base + wm * 64 + mi * 16 + tq + h * 8;
            const float pos = (float)((m & (SEQ - 1)) + 1);
            #pragma unroll
            for (int ni = 0; ni < 4; ni++) {
                const float xe = c[mi][ni][2 * h];
                const float xo = c[mi][ni][2 * h + 1];
                const int ncol = n_base + wn * 32 + ni * 8 + 2 * tr;
                if (region == 0) {
                    const int ii = ncol >> 1;
                    float sn, cs; sincosf(pos * g_theta[ii], &sn, &cs);
                    g_XQf[(long)m * FOLD + ii] = xe * (cs + sn) + xo * (cs - sn);
                } else if (region == 1) {
                    const int kk = ncol - 1024;
                    float sn, cs; sincosf(pos * g_theta[512 + (kk >> 1)], &sn, &cs);
                    *(float2*)(g_XK + (long)m * FOLD + kk) =
                        make_float2(xe * cs - xo * sn, xe * sn + xo * cs);
                } else {
                    const int vv = ncol - 1536;
                    *(float2*)(g_XV + (long)m * FOLD + vv) = make_float2(xe, xo);
                }
            }
        }
    }
}

// ---------------------------------------------------------------------------
// Kernel 2: prep — fold Wo pairwise + RoPE theta table (unchanged)
// ---------------------------------------------------------------------------
__global__ void prep(const float* __restrict__ Wo)
{
    const int idx = blockIdx.x * 256 + threadIdx.x;
    const int k = idx >> 10, n = idx & 1023;
    g_WoF[idx] = Wo[(2 * k) * IN_D + n] + Wo[(2 * k + 1) * IN_D + n];
    if (idx < 512)
        g_theta[idx] = (float)pow(10000.0, -(double)(2 * idx) / 1024.0);
    else if (idx < 768)
        g_theta[idx] = (float)pow(10000.0, -(double)(2 * (idx - 512)) / 512.0);
}

// ---------------------------------------------------------------------------
// Kernel 3: tensor-core flash attention, folded head dim 32.
// CTA = 128 q-rows x one (b,h). 8 warps, each warp owns 16 q-rows, full keys.
// QK^T: 3xTF32 (Q frags persistent in regs, K hi/lo in smem).
// softmax: no max subtraction (bounded logits); p = 2^t via exp2fast.
// PV: 1x tf32, raw-fp32 P bits; denominator via ones-column in V (bias-
// cancelling: same truncated p bits in numerator and denominator).
// grid (SEQ/128, BATCH*HEADS), 256 threads.
// ---------------------------------------------------------------------------
#define KV_STR 40   // smem row stride: bank(key,dim) patterns conflict-free

__global__ __launch_bounds__(256, 2) void attn_mma()
{
    __shared__ float Kh[64 * KV_STR];
    __shared__ float Kl[64 * KV_STR];
    __shared__ float Vv[64 * KV_STR];

    const int tid = threadIdx.x;
    const int wid = tid >> 5, lane = tid & 31;
    const int tq = lane >> 2, tr = lane & 3;
    const int h = blockIdx.y & (HEADS - 1);
    const int b = blockIdx.y >> 4;
    const int hoff = h * 32;
    const long kvbase = (long)b * SEQ;
    const int row0 = blockIdx.x * 128 + wid * 16 + tq;     // local q row
    const long gq = (kvbase + row0) * FOLD + hoff;

    // V ones-column for the softmax denominator (cols 33..39 zeroed: keeps
    // the unused accumulator lanes finite)
    if (tid < 64) {
        Vv[tid * KV_STR + 32] = 1.0f;
        #pragma unroll
        for (int z = 33; z < 40; z++) Vv[tid * KV_STR + z] = 0.0f;
    }

    // Q fragments (persistent): rows {row0, row0+8}, dims {ks*8+tr, +4},
    // pre-scaled by 0.5 * log2(e) so scores land in log2 domain.
    const float QS = 0.72134752044448170368f;
    uint32_t qh[4][4], ql[4][4];
    #pragma unroll
    for (int ks = 0; ks < 4; ks++) {
        const int d = ks * 8 + tr;
        float v[4];
        v[0] = g_XQf[gq + d] * QS;
        v[1] = g_XQf[gq + 8 * FOLD + d] * QS;
        v[2] = g_XQf[gq + d + 4] * QS;
        v[3] = g_XQf[gq + 8 * FOLD + d + 4] * QS;
        #pragma unroll
        for (int j = 0; j < 4; j++) {
            uint32_t hi = f2tf32(v[j]);
            qh[ks][j] = hi;
            ql[ks][j] = f2tf32(v[j] - __uint_as_float(hi));
        }
    }

    float c[5][4];
    #pragma unroll
    for (int i = 0; i < 5; i++)
        #pragma unroll
        for (int j = 0; j < 4; j++) c[i][j] = 0.f;

    // loader mapping: 4 threads per key row, 8 dims each
    const int lr = tid >> 2, lc = (tid & 3) * 8;

    for (int t0 = 0; t0 < SEQ; t0 += 64) {
        // ---- load K (hi/lo split) and V (raw) tiles ----
        {
            const float* kp = g_XK + (kvbase + t0 + lr) * FOLD + hoff + lc;
            const float* vp = g_XV + (kvbase + t0 + lr) * FOLD + hoff + lc;
            float4 a = *(const float4*)kp, bq = *(const float4*)(kp + 4);
            const float kv[8] = {a.x, a.y, a.z, a.w, bq.x, bq.y, bq.z, bq.w};
            #pragma unroll
            for (int j = 0; j < 8; j++) {
                uint32_t hi = f2tf32(kv[j]);
                ((uint32_t*)Kh)[lr * KV_STR + lc + j] = hi;
                ((uint32_t*)Kl)[lr * KV_STR + lc + j] =
                    f2tf32(kv[j] - __uint_as_float(hi));
            }
            float4 va = *(const float4*)vp, vb = *(const float4*)(vp + 4);
            *(float4*)&Vv[lr * KV_STR + lc] = va;
            *(float4*)&Vv[lr * KV_STR + lc + 4] = vb;
        }
        __syncthreads();

        // ---- S = Qf @ K^T (3xTF32), log2 domain ----
        float s[8][4];
        #pragma unroll
        for (int nt = 0; nt < 8; nt++)
            #pragma unroll
            for (int j = 0; j < 4; j++) s[nt][j] = 0.f;

        #pragma unroll
        for (int ks = 0; ks < 4; ks++) {
            #pragma unroll
            for (int nt = 0; nt < 8; nt++) {
                const int bi = (nt * 8 + tq) * KV_STR + ks * 8 + tr;
                uint32_t bh[2] = { ((uint32_t*)Kh)[bi], ((uint32_t*)Kh)[bi + 4] };
                uint32_t bl[2] = { ((uint32_t*)Kl)[bi], ((uint32_t*)Kl)[bi + 4] };
                mma_tf32(s[nt], ql[ks], bh);
                mma_tf32(s[nt], qh[ks], bl);
                mma_tf32(s[nt], qh[ks], bh);
            }
        }

        // ---- p = 2^s (FMA-pipe exp; no max subtraction needed) ----
        #pragma unroll
        for (int nt = 0; nt < 8; nt++)
            #pragma unroll
            for (int j = 0; j < 4; j++) s[nt][j] = exp2fast(s[nt][j]);

        // ---- ctx += P @ [V | 1] (1x tf32; raw fp32 P bits) ----
        const int sl = (lane & 28) | ((lane >> 1) & 1);   // tq*4 + (tr>>1)
        const bool odd = lane & 1;
        #pragma unroll
        for (int ks = 0; ks < 8; ks++) {
            float x0 = __shfl_sync(0xffffffffu, s[ks][0], sl);
            float x1 = __shfl_sync(0xffffffffu, s[ks][1], sl);
            float x2 = __shfl_sync(0xffffffffu, s[ks][2], sl);
            float x3 = __shfl_sync(0xffffffffu, s[ks][3], sl);
            float y0 = __shfl_sync(0xffffffffu, s[ks][0], sl + 2);
            float y1 = __shfl_sync(0xffffffffu, s[ks][1], sl + 2);
            float y2 = __shfl_sync(0xffffffffu, s[ks][2], sl + 2);
            float y3 = __shfl_sync(0xffffffffu, s[ks][3], sl + 2);
            uint32_t a[4];
            a[0] = __float_as_uint(odd ? x1 : x0);
            a[1] = __float_as_uint(odd ? x3 : x2);
            a[2] = __float_as_uint(odd ? y1 : y0);
            a[3] = __float_as_uint(odd ? y3 : y2);
            #pragma unroll
            for (int nt = 0; nt < 5; nt++) {
                const int vi = (ks * 8 + tr) * KV_STR + nt * 8 + tq;
                uint32_t bv[2] = { ((uint32_t*)Vv)[vi],
                                   ((uint32_t*)Vv)[vi + 4 * KV_STR] };
                mma_tf32(c[nt], a, bv);
            }
        }
        __syncthreads();
    }

    // ---- normalize and write ----
    const float l0 = __shfl_sync(0xffffffffu, c[4][0], lane & 28);
    const float l1 = __shfl_sync(0xffffffffu, c[4][2], lane & 28);
    const float i0 = 1.0f / l0, i1 = 1.0f / l1;
    #pragma unroll
    for (int nt = 0; nt < 4; nt++) {
        const int col = nt * 8 + 2 * tr;
        *(float2*)(g_CTX + gq + col) =
            make_float2(c[nt][0] * i0, c[nt][1] * i0);
        *(float2*)(g_CTX + gq + 8 * FOLD + col) =
            make_float2(c[nt][2] * i1, c[nt][3] * i1);
    }
}

// ---------------------------------------------------------------------------
// Kernel 4: output projection CTX @ WoF (3xTF32, unchanged)
// ---------------------------------------------------------------------------
__global__ __launch_bounds__(256) void gemm_out(float* __restrict__ C)
{
    extern __shared__ float sm[];

    const int tid = threadIdx.x;
    const int wid = tid >> 5, lane = tid & 31;
    const int wm = wid & 1, wn = wid >> 1;
    const int tq = lane >> 2, tr = lane & 3;
    const int m_base = blockIdx.y * 128;
    const int n_base = blockIdx.x * 128;

    float c[4][4][4];
    #pragma unroll
    for (int i = 0; i < 4; i++)
        #pragma unroll
        for (int j = 0; j < 4; j++)
            #pragma unroll
            for (int r = 0; r < 4; r++) c[i][j][r] = 0.f;

    gemm_mainloop(sm, g_CTX + (long)m_base * FOLD, FOLD,
                  g_WoF + n_base, IN_D, FOLD, tid, c);

    #pragma unroll
    for (int mi = 0; mi < 4; mi++)
        #pragma unroll
        for (int h = 0; h < 2; h++) {
            const int m = m_base + wm * 64 + mi * 16 + tq + h * 8;
            #pragma unroll
            for (int ni = 0; ni < 4; ni++) {
                const int col = n_base + wn * 32 + ni * 8 + 2 * tr;
                *(float2*)(C + (long)m * IN_D + col) =
                    make_float2(c[mi][ni][2 * h], c[mi][ni][2 * h + 1]);
            }
        }
}

// ---------------------------------------------------------------------------
extern "C" void kernel_launch(void* const* d_in, const int* in_sizes, int n_in,
                              void* d_out, int out_size)
{
    const float* q  = (const float*)d_in[0];
    const float* Wq = (const float*)d_in[1];
    const float* Wk = (const float*)d_in[2];
    const float* Wv = (const float*)d_in[3];
    const float* Wo = (const float*)d_in[4];

    static int configured = 0;
    if (!configured) {
        cudaFuncSetAttribute(gemm_qkv, cudaFuncAttributeMaxDynamicSharedMemorySize, GSMEM_BYTES);
        cudaFuncSetAttribute(gemm_out, cudaFuncAttributeMaxDynamicSharedMemorySize, GSMEM_BYTES);
        configured = 1;
    }

    prep    <<<2048, 256>>>(Wo);                                    // WoF + theta table
    gemm_qkv<<<dim3(16, 32), 256, GSMEM_BYTES>>>(q, Wq, Wk, Wv);    // 3xTF32 + rope
    attn_mma<<<dim3(SEQ / 128, BATCH * HEADS), 256>>>();            // tensor-core flash attn
    gemm_out<<<dim3(8, 32), 256, GSMEM_BYTES>>>((float*)d_out);     // 3xTF32
}

// round 10
// speedup vs baseline: 2.0789x; 1.3363x over previous
#include <cuda_runtime.h>
#include <math.h>
#include <cstdint>

// Problem constants
#define BATCH   2
#define SEQ     2048
#define HEADS   16
#define IN_D    1024
#define MROWS   (BATCH*SEQ)       // 4096
#define FOLD    512               // folded width

// Scratch (device globals; no allocation allowed)
__device__ __align__(256) float g_XQf[MROWS*FOLD];   // folded+rope'd Q  [4096,512]
__device__ __align__(256) float g_XK [MROWS*FOLD];   // rope'd K         [4096,512]
__device__ __align__(256) float g_XV [MROWS*FOLD];   // V                [4096,512]
__device__ __align__(256) float g_CTX[MROWS*FOLD];   // attention ctx    [4096,512]
__device__ __align__(256) float g_WoF[FOLD*IN_D];    // folded Wo        [512,1024]
__device__ float g_theta[768];                       // [0,512): Q pair thetas, [512,768): K

// ---------------------------------------------------------------------------
// Helpers
// ---------------------------------------------------------------------------
__device__ __forceinline__ uint32_t smem_u32(const void* p) {
    uint32_t a;
    asm("{ .reg .u64 t; cvta.to.shared.u64 t, %1; cvt.u32.u64 %0, t; }" : "=r"(a) : "l"(p));
    return a;
}

// Truncation hi/lo split for 3xTF32: hi = x with low 13 mantissa bits zeroed
// (exact LOP), lo = x - hi (exact FADD; HW truncates lo to tf32 inside the MMA,
// residual ~2^-20 relative — negligible at our error budget).
__device__ __forceinline__ void split_hl(float x, uint32_t& h, uint32_t& l) {
    h = __float_as_uint(x) & 0xFFFFE000u;
    l = __float_as_uint(x - __uint_as_float(h));
}

__device__ __forceinline__ void mma_tf32(float* d, const uint32_t* a, const uint32_t* b) {
    asm volatile(
        "mma.sync.aligned.m16n8k8.row.col.f32.tf32.tf32.f32 "
        "{%0,%1,%2,%3}, {%4,%5,%6,%7}, {%8,%9}, {%0,%1,%2,%3};"
        : "+f"(d[0]), "+f"(d[1]), "+f"(d[2]), "+f"(d[3])
        : "r"(a[0]), "r"(a[1]), "r"(a[2]), "r"(a[3]), "r"(b[0]), "r"(b[1]));
}

// fast 2^t on the FMA/ALU pipes (no MUFU): magic-round + degree-5 Taylor.
__device__ __forceinline__ float exp2fast(float t) {
    float z = t + 12582912.0f;                 // 1.5*2^23
    int   n = __float_as_int(z) - 0x4B400000;
    float f = t - (z - 12582912.0f);           // f in [-0.5, 0.5]
    float r = 1.0f + f*(0.69314718f + f*(0.24022651f + f*(0.05550411f
                  + f*(0.00961813f + f*0.00133336f))));
    return __int_as_float(__float_as_int(r) + (n << 23));
}

// cp.async (LDGSTS) primitives
#define CPA16(dst, src) \
    asm volatile("cp.async.cg.shared.global [%0], [%1], 16;" :: "r"(dst), "l"(src) : "memory")
#define CP_COMMIT() asm volatile("cp.async.commit_group;" ::: "memory")
#define CP_WAIT1()  asm volatile("cp.async.wait_group 1;" ::: "memory")
#define CP_WAIT0()  asm volatile("cp.async.wait_group 0;" ::: "memory")

// Smem strides (floats) chosen for conflict-free fragment LDS:
//   A[m][k]: stride 36 -> bank(m,k) = (4m+k)%32, distinct over the 8x4 lane grid
//   B[k][n]: stride 136 -> bank(k,n) = (8k+n)%32, distinct over the 4x8 lane grid
#define A_STR 36
#define B_STR 136
#define A_ELEMS (128 * A_STR)
#define B_ELEMS (32 * B_STR)
#define BUF_FLOATS (A_ELEMS + B_ELEMS)
#define GSMEM_BYTES (2 * BUF_FLOATS * 4)   // raw fp32, double-buffered: 71680 B

// ---------------------------------------------------------------------------
// 3xTF32 tile GEMM mainloop, v2: raw fp32 tiles via cp.async double buffering,
// hi/lo split in registers at fragment-load time.
// CTA tile 128x128, BK=32, 256 threads (8 warps 2x4), warp tile 64x32.
// ---------------------------------------------------------------------------
__device__ __forceinline__ void gemm_mainloop(
    float* sm, uint32_t smb,
    const float* __restrict__ A, int lda,
    const float* __restrict__ B, int ldb,
    int nk, int tid, float c[4][4][4])
{
    const int wid = tid >> 5, lane = tid & 31;
    const int wm = wid & 1, wn = wid >> 1;
    const int tq = lane >> 2, tr = lane & 3;
    const int nit = nk / 32;

    auto load_tile = [&](int buf, int k0) {
        uint32_t as = smb + buf * (BUF_FLOATS * 4);
        uint32_t bs = as + A_ELEMS * 4;
        #pragma unroll
        for (int i = 0; i < 4; i++) {
            int e = i * 256 + tid;
            int r = e >> 3, c4 = e & 7;
            CPA16(as + (uint32_t)(r * A_STR + c4 * 4) * 4,
                  A + (long)r * lda + k0 + c4 * 4);
        }
        #pragma unroll
        for (int i = 0; i < 4; i++) {
            int e = i * 256 + tid;
            int kr = e >> 5, c4 = e & 31;
            CPA16(bs + (uint32_t)(kr * B_STR + c4 * 4) * 4,
                  B + (long)(k0 + kr) * ldb + c4 * 4);
        }
        CP_COMMIT();
    };

    load_tile(0, 0);
    for (int it = 0; it < nit; it++) {
        if (it + 1 < nit) { load_tile((it + 1) & 1, (it + 1) * 32); CP_WAIT1(); }
        else              { CP_WAIT0(); }
        __syncthreads();

        const float* As = sm + (it & 1) * BUF_FLOATS;
        const float* Bs = As + A_ELEMS;

        #pragma unroll
        for (int ks = 0; ks < 4; ks++) {
            uint32_t ah[4][4], al[4][4], bh[4][2], bl[4][2];
            #pragma unroll
            for (int mi = 0; mi < 4; mi++) {
                int base = (wm * 64 + mi * 16 + tq) * A_STR + ks * 8 + tr;
                split_hl(As[base],                 ah[mi][0], al[mi][0]);
                split_hl(As[base + 8 * A_STR],     ah[mi][1], al[mi][1]);
                split_hl(As[base + 4],             ah[mi][2], al[mi][2]);
                split_hl(As[base + 8 * A_STR + 4], ah[mi][3], al[mi][3]);
            }
            #pragma unroll
            for (int ni = 0; ni < 4; ni++) {
                int base = (ks * 8 + tr) * B_STR + wn * 32 + ni * 8 + tq;
                split_hl(Bs[base],             bh[ni][0], bl[ni][0]);
                split_hl(Bs[base + 4 * B_STR], bh[ni][1], bl[ni][1]);
            }
            #pragma unroll
            for (int mi = 0; mi < 4; mi++)
                #pragma unroll
                for (int ni = 0; ni < 4; ni++) {
                    mma_tf32(c[mi][ni], al[mi], bh[ni]);
                    mma_tf32(c[mi][ni], ah[mi], bl[ni]);
                    mma_tf32(c[mi][ni], ah[mi], bh[ni]);
                }
        }
        __syncthreads();
    }
}

// ---------------------------------------------------------------------------
// Kernel 1: QKV projection (3xTF32) + RoPE/fold on fragments
// ---------------------------------------------------------------------------
__global__ __launch_bounds__(256) void gemm_qkv(
    const float* __restrict__ A,
    const float* __restrict__ Wq,
    const float* __restrict__ Wk,
    const float* __restrict__ Wv)
{
    extern __shared__ float sm[];
    uint32_t smb = smem_u32(sm);

    const int tid = threadIdx.x;
    const int wid = tid >> 5, lane = tid & 31;
    const int wm = wid & 1, wn = wid >> 1;
    const int tq = lane >> 2, tr = lane & 3;
    const int m_base = blockIdx.y * 128;
    const int n_base = blockIdx.x * 128;

    const float* Bm; int ldb, region;
    if (n_base < 1024)      { Bm = Wq + n_base;          ldb = 1024; region = 0; }
    else if (n_base < 1536) { Bm = Wk + (n_base - 1024); ldb = 512;  region = 1; }
    else                    { Bm = Wv + (n_base - 1536); ldb = 512;  region = 2; }

    float c[4][4][4];
    #pragma unroll
    for (int i = 0; i < 4; i++)
        #pragma unroll
        for (int j = 0; j < 4; j++)
            #pragma unroll
            for (int r = 0; r < 4; r++) c[i][j][r] = 0.f;

    gemm_mainloop(sm, smb, A + (long)m_base * IN_D, IN_D, Bm, ldb, IN_D, tid, c);

    #pragma unroll
    for (int mi = 0; mi < 4; mi++) {
        #pragma unroll
        for (int h = 0; h < 2; h++) {
            const int m = m_base + wm * 64 + mi * 16 + tq + h * 8;
            const float pos = (float)((m & (SEQ - 1)) + 1);
            #pragma unroll
            for (int ni = 0; ni < 4; ni++) {
                const float xe = c[mi][ni][2 * h];
                const float xo = c[mi][ni][2 * h + 1];
                const int ncol = n_base + wn * 32 + ni * 8 + 2 * tr;
                if (region == 0) {
                    const int ii = ncol >> 1;
                    float sn, cs; sincosf(pos * g_theta[ii], &sn, &cs);
                    g_XQf[(long)m * FOLD + ii] = xe * (cs + sn) + xo * (cs - sn);
                } else if (region == 1) {
                    const int kk = ncol - 1024;
                    float sn, cs; sincosf(pos * g_theta[512 + (kk >> 1)], &sn, &cs);
                    *(float2*)(g_XK + (long)m * FOLD + kk) =
                        make_float2(xe * cs - xo * sn, xe * sn + xo * cs);
                } else {
                    const int vv = ncol - 1536;
                    *(float2*)(g_XV + (long)m * FOLD + vv) = make_float2(xe, xo);
                }
            }
        }
    }
}

// ---------------------------------------------------------------------------
// Kernel 2: prep — fold Wo pairwise + RoPE theta table
// ---------------------------------------------------------------------------
__global__ void prep(const float* __restrict__ Wo)
{
    const int idx = blockIdx.x * 256 + threadIdx.x;
    const int k = idx >> 10, n = idx & 1023;
    g_WoF[idx] = Wo[(2 * k) * IN_D + n] + Wo[(2 * k + 1) * IN_D + n];
    if (idx < 512)
        g_theta[idx] = (float)pow(10000.0, -(double)(2 * idx) / 1024.0);
    else if (idx < 768)
        g_theta[idx] = (float)pow(10000.0, -(double)(2 * (idx - 512)) / 512.0);
}

// ---------------------------------------------------------------------------
// Kernel 3: tensor-core flash attention, folded head dim 32, v2:
// raw K/V tiles via cp.async double-buffering, K hi/lo split in registers.
// softmax: no max subtraction (bounded logits); p = 2^t on FMA pipe; softmax
// denominator via ones-column through the same PV MMA (bias cancels).
// grid (SEQ/128, BATCH*HEADS), 256 threads, 2 CTAs/SM.
// ---------------------------------------------------------------------------
#define KV_STR 40   // conflict-free row stride

__global__ __launch_bounds__(256, 2) void attn_mma()
{
    __shared__ float Kr[2][64 * KV_STR];
    __shared__ float Vv[2][64 * KV_STR];

    const int tid = threadIdx.x;
    const int wid = tid >> 5, lane = tid & 31;
    const int tq = lane >> 2, tr = lane & 3;
    const int h = blockIdx.y & (HEADS - 1);
    const int b = blockIdx.y >> 4;
    const int hoff = h * 32;
    const long kvbase = (long)b * SEQ;
    const int row0 = blockIdx.x * 128 + wid * 16 + tq;
    const long gq = (kvbase + row0) * FOLD + hoff;

    // ones-column for the denominator (cols 32..39; cp.async writes only 0..31)
    if (tid < 64) {
        #pragma unroll
        for (int bb = 0; bb < 2; bb++) {
            Vv[bb][tid * KV_STR + 32] = 1.0f;
            #pragma unroll
            for (int z = 33; z < 40; z++) Vv[bb][tid * KV_STR + z] = 0.0f;
        }
    }

    // Q fragments (persistent, trunc hi/lo split), pre-scaled by 0.5*log2(e)
    const float QS = 0.72134752044448170368f;
    uint32_t qh[4][4], ql[4][4];
    #pragma unroll
    for (int ks = 0; ks < 4; ks++) {
        const int d = ks * 8 + tr;
        float v[4];
        v[0] = g_XQf[gq + d] * QS;
        v[1] = g_XQf[gq + 8 * FOLD + d] * QS;
        v[2] = g_XQf[gq + d + 4] * QS;
        v[3] = g_XQf[gq + 8 * FOLD + d + 4] * QS;
        #pragma unroll
        for (int j = 0; j < 4; j++) split_hl(v[j], qh[ks][j], ql[ks][j]);
    }

    float c[5][4];
    #pragma unroll
    for (int i = 0; i < 5; i++)
        #pragma unroll
        for (int j = 0; j < 4; j++) c[i][j] = 0.f;

    // loader mapping: 4 threads per key row, 8 dims each
    const int lr = tid >> 2, lc = (tid & 3) * 8;
    const uint32_t kbu = smem_u32(&Kr[0][0]);
    const uint32_t vbu = smem_u32(&Vv[0][0]);

    auto load_kv = [&](int buf, int t0) {
        const float* kp = g_XK + (kvbase + t0 + lr) * FOLD + hoff + lc;
        const float* vp = g_XV + (kvbase + t0 + lr) * FOLD + hoff + lc;
        const uint32_t off = (uint32_t)(buf * 64 * KV_STR + lr * KV_STR + lc) * 4;
        CPA16(kbu + off, kp);  CPA16(kbu + off + 16, kp + 4);
        CPA16(vbu + off, vp);  CPA16(vbu + off + 16, vp + 4);
        CP_COMMIT();
    };

    load_kv(0, 0);
    const int nit = SEQ / 64;
    for (int it = 0; it < nit; it++) {
        if (it + 1 < nit) { load_kv((it + 1) & 1, (it + 1) * 64); CP_WAIT1(); }
        else              { CP_WAIT0(); }
        __syncthreads();

        const float* Kb = Kr[it & 1];
        const float* Vb = Vv[it & 1];

        // ---- S = Qf @ K^T (3xTF32), log2 domain ----
        float s[8][4];
        #pragma unroll
        for (int nt = 0; nt < 8; nt++)
            #pragma unroll
            for (int j = 0; j < 4; j++) s[nt][j] = 0.f;

        #pragma unroll
        for (int ks = 0; ks < 4; ks++) {
            #pragma unroll
            for (int nt = 0; nt < 8; nt++) {
                const int bi = (nt * 8 + tq) * KV_STR + ks * 8 + tr;
                uint32_t bh[2], bl[2];
                split_hl(Kb[bi],     bh[0], bl[0]);
                split_hl(Kb[bi + 4], bh[1], bl[1]);
                mma_tf32(s[nt], ql[ks], bh);
                mma_tf32(s[nt], qh[ks], bl);
                mma_tf32(s[nt], qh[ks], bh);
            }
        }

        // ---- p = 2^s on the FMA pipe ----
        #pragma unroll
        for (int nt = 0; nt < 8; nt++)
            #pragma unroll
            for (int j = 0; j < 4; j++) s[nt][j] = exp2fast(s[nt][j]);

        // ---- ctx += P @ [V | 1] (1x tf32; raw fp32 P bits) ----
        const int sl = (lane & 28) | ((lane >> 1) & 1);
        const bool odd = lane & 1;
        #pragma unroll
        for (int ks = 0; ks < 8; ks++) {
            float x0 = __shfl_sync(0xffffffffu, s[ks][0], sl);
            float x1 = __shfl_sync(0xffffffffu, s[ks][1], sl);
            float x2 = __shfl_sync(0xffffffffu, s[ks][2], sl);
            float x3 = __shfl_sync(0xffffffffu, s[ks][3], sl);
            float y0 = __shfl_sync(0xffffffffu, s[ks][0], sl + 2);
            float y1 = __shfl_sync(0xffffffffu, s[ks][1], sl + 2);
            float y2 = __shfl_sync(0xffffffffu, s[ks][2], sl + 2);
            float y3 = __shfl_sync(0xffffffffu, s[ks][3], sl + 2);
            uint32_t a[4];
            a[0] = __float_as_uint(odd ? x1 : x0);
            a[1] = __float_as_uint(odd ? x3 : x2);
            a[2] = __float_as_uint(odd ? y1 : y0);
            a[3] = __float_as_uint(odd ? y3 : y2);
            #pragma unroll
            for (int nt = 0; nt < 5; nt++) {
                const int vi = (ks * 8 + tr) * KV_STR + nt * 8 + tq;
                uint32_t bv[2] = { ((const uint32_t*)Vb)[vi],
                                   ((const uint32_t*)Vb)[vi + 4 * KV_STR] };
                mma_tf32(c[nt], a, bv);
            }
        }
        __syncthreads();
    }

    // ---- normalize and write ----
    const float l0 = __shfl_sync(0xffffffffu, c[4][0], lane & 28);
    const float l1 = __shfl_sync(0xffffffffu, c[4][2], lane & 28);
    const float i0 = 1.0f / l0, i1 = 1.0f / l1;
    #pragma unroll
    for (int nt = 0; nt < 4; nt++) {
        const int col = nt * 8 + 2 * tr;
        *(float2*)(g_CTX + gq + col) =
            make_float2(c[nt][0] * i0, c[nt][1] * i0);
        *(float2*)(g_CTX + gq + 8 * FOLD + col) =
            make_float2(c[nt][2] * i1, c[nt][3] * i1);
    }
}

// ---------------------------------------------------------------------------
// Kernel 4: output projection CTX @ WoF (3xTF32)
// ---------------------------------------------------------------------------
__global__ __launch_bounds__(256) void gemm_out(float* __restrict__ C)
{
    extern __shared__ float sm[];
    uint32_t smb = smem_u32(sm);

    const int tid = threadIdx.x;
    const int wid = tid >> 5, lane = tid & 31;
    const int wm = wid & 1, wn = wid >> 1;
    const int tq = lane >> 2, tr = lane & 3;
    const int m_base = blockIdx.y * 128;
    const int n_base = blockIdx.x * 128;

    float c[4][4][4];
    #pragma unroll
    for (int i = 0; i < 4; i++)
        #pragma unroll
        for (int j = 0; j < 4; j++)
            #pragma unroll
            for (int r = 0; r < 4; r++) c[i][j][r] = 0.f;

    gemm_mainloop(sm, smb, g_CTX + (long)m_base * FOLD, FOLD,
                  g_WoF + n_base, IN_D, FOLD, tid, c);

    #pragma unroll
    for (int mi = 0; mi < 4; mi++)
        #pragma unroll
        for (int h = 0; h < 2; h++) {
            const int m = m_base + wm * 64 + mi * 16 + tq + h * 8;
            #pragma unroll
            for (int ni = 0; ni < 4; ni++) {
                const int col = n_base + wn * 32 + ni * 8 + 2 * tr;
                *(float2*)(C + (long)m * IN_D + col) =
                    make_float2(c[mi][ni][2 * h], c[mi][ni][2 * h + 1]);
            }
        }
}

// ---------------------------------------------------------------------------
extern "C" void kernel_launch(void* const* d_in, const int* in_sizes, int n_in,
                              void* d_out, int out_size)
{
    const float* q  = (const float*)d_in[0];
    const float* Wq = (const float*)d_in[1];
    const float* Wk = (const float*)d_in[2];
    const float* Wv = (const float*)d_in[3];
    const float* Wo = (const float*)d_in[4];

    static int configured = 0;
    if (!configured) {
        cudaFuncSetAttribute(gemm_qkv, cudaFuncAttributeMaxDynamicSharedMemorySize, GSMEM_BYTES);
        cudaFuncSetAttribute(gemm_out, cudaFuncAttributeMaxDynamicSharedMemorySize, GSMEM_BYTES);
        configured = 1;
    }

    prep    <<<2048, 256>>>(Wo);                                    // WoF + theta table
    gemm_qkv<<<dim3(16, 32), 256, GSMEM_BYTES>>>(q, Wq, Wk, Wv);    // 3xTF32 + rope
    attn_mma<<<dim3(SEQ / 128, BATCH * HEADS), 256>>>();            // tensor-core flash attn
    gemm_out<<<dim3(8, 32), 256, GSMEM_BYTES>>>((float*)d_out);     // 3xTF32
}